// round 1
// baseline (speedup 1.0000x reference)
#include <cuda_runtime.h>
#include <cuda_bf16.h>

#define NN 100000
#define EE 1600000
#define HID 128
#define FIN 100
#define CLS 47

typedef unsigned long long ull;

// ---------------- device scratch (no allocs allowed) ----------------
__device__ int   g_deg[NN];
__device__ int   g_rowstart[NN];
__device__ int   g_pos[NN];
__device__ int   g_bsums[128];
__device__ int   g_permsrc[EE];
__device__ float g_permw[EE];
__device__ float g_agg0[(size_t)NN * FIN];
__device__ float g_agg [(size_t)NN * HID];
__device__ float g_x1  [(size_t)NN * HID];
__device__ float g_x2  [(size_t)NN * HID];
__device__ float g_x3  [(size_t)NN * HID];

// ---------------- CSR build ----------------
__global__ void k_zero_deg() {
    int i = blockIdx.x * 256 + threadIdx.x;
    if (i < NN) g_deg[i] = 0;
}

__global__ void k_count(const int* __restrict__ dst) {
    int e = blockIdx.x * 256 + threadIdx.x;
    if (e < EE) atomicAdd(&g_deg[dst[e]], 1);
}

__global__ void k_scanA() {
    __shared__ int s[1024];
    int tid = threadIdx.x;
    int i = blockIdx.x * 1024 + tid;
    int v = (i < NN) ? g_deg[i] : 0;
    s[tid] = v;
    __syncthreads();
    for (int off = 1; off < 1024; off <<= 1) {
        int a = s[tid];
        int b = (tid >= off) ? s[tid - off] : 0;
        __syncthreads();
        s[tid] = a + b;
        __syncthreads();
    }
    if (i < NN) g_rowstart[i] = s[tid] - v;     // exclusive within block
    if (tid == 1023) g_bsums[blockIdx.x] = s[1023];
}

__global__ void k_scanB(int nb) {
    if (threadIdx.x == 0) {
        int run = 0;
        for (int b = 0; b < nb; b++) { int t = g_bsums[b]; g_bsums[b] = run; run += t; }
    }
}

__global__ void k_scanC() {
    int i = blockIdx.x * 256 + threadIdx.x;
    if (i < NN) {
        int r = g_rowstart[i] + g_bsums[i >> 10];
        g_rowstart[i] = r;
        g_pos[i] = r;
    }
}

__global__ void k_fill(const int* __restrict__ src, const int* __restrict__ dst,
                       const float* __restrict__ w) {
    int e = blockIdx.x * 256 + threadIdx.x;
    if (e >= EE) return;
    int d = dst[e];
    int p = atomicAdd(&g_pos[d], 1);
    g_permsrc[p] = src[e];
    g_permw[p] = w[e];
}

// ---------------- aggregation: warp per node, no atomics ----------------
template <int D>
__global__ void k_aggregate(const float* __restrict__ x, float* __restrict__ agg) {
    int gt = blockIdx.x * blockDim.x + threadIdx.x;
    int node = gt >> 5;
    int lane = gt & 31;
    if (node >= NN) return;
    int start = g_rowstart[node];
    int cnt = g_deg[node];
    constexpr int NV = D / 4;
    bool act = lane < NV;
    float4 acc = make_float4(0.f, 0.f, 0.f, 0.f);
    int snext = 0; float wnext = 0.f;
    if (cnt > 0) { snext = __ldg(&g_permsrc[start]); wnext = __ldg(&g_permw[start]); }
    for (int i = 0; i < cnt; i++) {
        int s = snext; float wv = wnext;
        if (i + 1 < cnt) {
            snext = __ldg(&g_permsrc[start + i + 1]);
            wnext = __ldg(&g_permw[start + i + 1]);
        }
        if (act) {
            float4 v = __ldg(reinterpret_cast<const float4*>(x + (size_t)s * D) + lane);
            acc.x += v.x * wv; acc.y += v.y * wv; acc.z += v.z * wv; acc.w += v.w * wv;
        }
    }
    if (act) reinterpret_cast<float4*>(agg + (size_t)node * D)[lane] = acc;
}

// ---------------- fused dual GEMM + bias + relu (f32x2 packed FMA) -----------
// out[n,c] = relu( sum_k A[n,k]*Wrel[c,k] + X[n,k]*Wroot[c,k] + b[c] ), c<128
// Block: 64 rows x 128 cols, 256 threads, thread = 8 rows x 4 cols (cols strided 32).
__global__ __launch_bounds__(256, 1) void k_gemm_dual(
    const float* __restrict__ A, const float* __restrict__ X,
    const float* __restrict__ Wrel, const float* __restrict__ Wroot,
    const float* __restrict__ bias, float* __restrict__ out, int K)
{
    extern __shared__ __align__(16) float sm[];
    const int K2 = K >> 1;
    const int Kpad = K + 2;
    ull* Wrp = (ull*)sm;                  // [K2][129] float2 pairs of Wrel
    ull* Wtp = Wrp + K2 * 129;            // same for Wroot
    float* Aagg = (float*)(Wtp + K2 * 129);   // [64][Kpad]
    float* Ax   = Aagg + 64 * Kpad;           // [64][Kpad]
    float* bs   = Ax + 64 * Kpad;             // [128]

    int t = threadIdx.x;
    int row0 = blockIdx.x * 64;

    // load weights pair-packed: Wrp[k2*129+c] = (W[c][2k2], W[c][2k2+1])
    for (int s = t; s < 128 * K2; s += 256) {
        int c = s / K2;
        int k2 = s - c * K2;
        Wrp[k2 * 129 + c] = *(const ull*)(Wrel + c * K + 2 * k2);
        Wtp[k2 * 129 + c] = *(const ull*)(Wroot + c * K + 2 * k2);
    }
    // load A / X tiles row-major
    for (int s = t; s < 64 * K; s += 256) {
        int r = s / K;
        int k = s - r * K;
        int row = row0 + r;
        float va = 0.f, vx = 0.f;
        if (row < NN) {
            va = A[(size_t)row * K + k];
            vx = X[(size_t)row * K + k];
        }
        Aagg[r * Kpad + k] = va;
        Ax[r * Kpad + k] = vx;
    }
    if (t < 128) bs[t] = bias[t];
    __syncthreads();

    int tc = t & 31;
    int tr = t >> 5;
    ull acc[8][4];
#pragma unroll
    for (int i = 0; i < 8; i++)
#pragma unroll
        for (int j = 0; j < 4; j++) acc[i][j] = 0ull;

    const float* Ar = Aagg + (tr * 8) * Kpad;
    const float* Xr = Ax + (tr * 8) * Kpad;

    for (int k2 = 0; k2 < K2; k2++) {
        ull aA[8], aX[8];
#pragma unroll
        for (int i = 0; i < 8; i++) {
            aA[i] = *(const ull*)(Ar + i * Kpad + 2 * k2);   // broadcast
            aX[i] = *(const ull*)(Xr + i * Kpad + 2 * k2);
        }
        ull wR[4], wT[4];
#pragma unroll
        for (int j = 0; j < 4; j++) {
            wR[j] = Wrp[k2 * 129 + tc + 32 * j];            // conflict-free
            wT[j] = Wtp[k2 * 129 + tc + 32 * j];
        }
#pragma unroll
        for (int i = 0; i < 8; i++)
#pragma unroll
            for (int j = 0; j < 4; j++) {
                asm("fma.rn.f32x2 %0, %1, %2, %0;" : "+l"(acc[i][j]) : "l"(aA[i]), "l"(wR[j]));
                asm("fma.rn.f32x2 %0, %1, %2, %0;" : "+l"(acc[i][j]) : "l"(aX[i]), "l"(wT[j]));
            }
    }

#pragma unroll
    for (int i = 0; i < 8; i++) {
        int row = row0 + tr * 8 + i;
        if (row >= NN) continue;
#pragma unroll
        for (int j = 0; j < 4; j++) {
            int c = tc + 32 * j;
            float lo = __uint_as_float((unsigned)acc[i][j]);
            float hi = __uint_as_float((unsigned)(acc[i][j] >> 32));
            float v = lo + hi + bs[c];
            out[(size_t)row * HID + c] = fmaxf(v, 0.f);
        }
    }
}

// ---------------- head: [x1|x2|x3] @ Wlin^T + b, log_softmax ----------------
__global__ __launch_bounds__(256, 1) void k_final(
    const float* __restrict__ Wlin, const float* __restrict__ blin,
    float* __restrict__ out)
{
    extern __shared__ __align__(16) float sm[];
    float* Wl = sm;                // [47][385]
    float* xs = Wl + CLS * 385;    // [8][385]
    float* bl = xs + 8 * 385;      // [47]
    int t = threadIdx.x;
    for (int s = t; s < CLS * 384; s += 256) {
        int c = s / 384;
        int k = s - c * 384;
        Wl[c * 385 + k] = Wlin[s];
    }
    if (t < CLS) bl[t] = blin[t];
    __syncthreads();

    int lane = t & 31;
    int wid = t >> 5;
    int n = blockIdx.x * 8 + wid;   // N = 100000 = 12500*8, exact
    float* xrow = xs + wid * 385;
    for (int k = lane; k < HID; k += 32) {
        xrow[k]       = g_x1[(size_t)n * HID + k];
        xrow[128 + k] = g_x2[(size_t)n * HID + k];
        xrow[256 + k] = g_x3[(size_t)n * HID + k];
    }
    __syncwarp();

    int c0 = lane;
    int c1 = lane + 32;
    bool h1 = c1 < CLS;
    float a0 = 0.f, a1 = 0.f;
    const float* w0 = Wl + c0 * 385;
    const float* w1 = Wl + c1 * 385;
    for (int k = 0; k < 384; k++) {
        float xv = xrow[k];
        a0 += xv * w0[k];
        if (h1) a1 += xv * w1[k];
    }
    a0 += bl[c0];
    if (h1) a1 += bl[c1];

    float m = h1 ? fmaxf(a0, a1) : a0;
    for (int o = 16; o > 0; o >>= 1) m = fmaxf(m, __shfl_xor_sync(0xffffffffu, m, o));
    float se = expf(a0 - m) + (h1 ? expf(a1 - m) : 0.f);
    for (int o = 16; o > 0; o >>= 1) se += __shfl_xor_sync(0xffffffffu, se, o);
    float lse = m + logf(se);

    out[(size_t)n * CLS + c0] = a0 - lse;
    if (h1) out[(size_t)n * CLS + c1] = a1 - lse;
}

// ---------------- launch ----------------
extern "C" void kernel_launch(void* const* d_in, const int* in_sizes, int n_in,
                              void* d_out, int out_size)
{
    const float* x0    = (const float*)d_in[0];
    const int*   ei    = (const int*)  d_in[1];
    const float* ew    = (const float*)d_in[2];
    const float* W1rel = (const float*)d_in[3];
    const float* W1rt  = (const float*)d_in[4];
    const float* b1    = (const float*)d_in[5];
    const float* W2rel = (const float*)d_in[6];
    const float* W2rt  = (const float*)d_in[7];
    const float* b2    = (const float*)d_in[8];
    const float* W3rel = (const float*)d_in[9];
    const float* W3rt  = (const float*)d_in[10];
    const float* b3    = (const float*)d_in[11];
    const float* Wlin  = (const float*)d_in[12];
    const float* blin  = (const float*)d_in[13];
    float* out = (float*)d_out;

    const int* src = ei;
    const int* dst = ei + EE;

    float *agg0p, *aggp, *x1p, *x2p, *x3p;
    cudaGetSymbolAddress((void**)&agg0p, g_agg0);
    cudaGetSymbolAddress((void**)&aggp,  g_agg);
    cudaGetSymbolAddress((void**)&x1p,   g_x1);
    cudaGetSymbolAddress((void**)&x2p,   g_x2);
    cudaGetSymbolAddress((void**)&x3p,   g_x3);

    const int smem128 = (128 * 258 + 128 * 130 + 128) * 4;   // 199168 B
    const int smem100 = (100 * 258 + 128 * 102 + 128) * 4;   // 155936 B
    const int smemF   = (CLS * 385 + 8 * 385 + 64) * 4;      //  84956 B
    cudaFuncSetAttribute(k_gemm_dual, cudaFuncAttributeMaxDynamicSharedMemorySize, smem128);
    cudaFuncSetAttribute(k_final,     cudaFuncAttributeMaxDynamicSharedMemorySize, smemF);

    // CSR build (per launch; deterministic up to fp-neutral edge permutation)
    k_zero_deg<<<(NN + 255) / 256, 256>>>();
    k_count<<<EE / 256, 256>>>(dst);
    k_scanA<<<(NN + 1023) / 1024, 1024>>>();
    k_scanB<<<1, 32>>>((NN + 1023) / 1024);
    k_scanC<<<(NN + 255) / 256, 256>>>();
    k_fill<<<EE / 256, 256>>>(src, dst, ew);

    const int aggBlocks = NN * 32 / 256;      // warp per node
    const int gemmBlocks = (NN + 63) / 64;

    // layer 1 (K = 100)
    k_aggregate<FIN><<<aggBlocks, 256>>>(x0, agg0p);
    k_gemm_dual<<<gemmBlocks, 256, smem100>>>(agg0p, x0, W1rel, W1rt, b1, x1p, FIN);
    // layer 2
    k_aggregate<HID><<<aggBlocks, 256>>>(x1p, aggp);
    k_gemm_dual<<<gemmBlocks, 256, smem128>>>(aggp, x1p, W2rel, W2rt, b2, x2p, HID);
    // layer 3
    k_aggregate<HID><<<aggBlocks, 256>>>(x2p, aggp);
    k_gemm_dual<<<gemmBlocks, 256, smem128>>>(aggp, x2p, W3rel, W3rt, b3, x3p, HID);
    // head
    k_final<<<NN / 8, 256, smemF>>>(Wlin, blin, out);
}

// round 2
// speedup vs baseline: 1.2522x; 1.2522x over previous
#include <cuda_runtime.h>
#include <cuda_bf16.h>

#define NN 100000
#define EE 1600000
#define HID 128
#define FIN 100
#define CLS 47

typedef unsigned long long ull;

// ---------------- device scratch (no allocs allowed) ----------------
__device__ int   g_deg[NN];
__device__ int   g_rowstart[NN];
__device__ int   g_pos[NN];
__device__ int   g_bsums[128];
__device__ int   g_permsrc[EE];
__device__ float g_permw[EE];
__device__ float g_agg0[(size_t)NN * FIN];
__device__ float g_agg [(size_t)NN * HID];
__device__ float g_x1  [(size_t)NN * HID];
__device__ float g_x2  [(size_t)NN * HID];
__device__ float g_x3  [(size_t)NN * HID];

__device__ __forceinline__ void fma2(ull &acc, ull a, ull b) {
    asm("fma.rn.f32x2 %0, %1, %2, %0;" : "+l"(acc) : "l"(a), "l"(b));
}
__device__ __forceinline__ ull pk(float x, float y) {
    ull r; asm("mov.b64 %0, {%1, %2};" : "=l"(r) : "f"(x), "f"(y)); return r;
}

// ---------------- CSR build ----------------
__global__ void k_zero_deg() {
    int i = blockIdx.x * 256 + threadIdx.x;
    if (i < NN) g_deg[i] = 0;
}

__global__ void k_count(const int* __restrict__ dst) {
    int e = blockIdx.x * 256 + threadIdx.x;
    if (e < EE) atomicAdd(&g_deg[dst[e]], 1);
}

__global__ void k_scanA() {
    __shared__ int s[1024];
    int tid = threadIdx.x;
    int i = blockIdx.x * 1024 + tid;
    int v = (i < NN) ? g_deg[i] : 0;
    s[tid] = v;
    __syncthreads();
    for (int off = 1; off < 1024; off <<= 1) {
        int a = s[tid];
        int b = (tid >= off) ? s[tid - off] : 0;
        __syncthreads();
        s[tid] = a + b;
        __syncthreads();
    }
    if (i < NN) g_rowstart[i] = s[tid] - v;
    if (tid == 1023) g_bsums[blockIdx.x] = s[1023];
}

__global__ void k_scanB(int nb) {   // parallel exclusive scan of block sums (nb<=128)
    __shared__ int s[128];
    int t = threadIdx.x;
    int v = (t < nb) ? g_bsums[t] : 0;
    s[t] = v;
    __syncthreads();
    for (int off = 1; off < 128; off <<= 1) {
        int a = s[t];
        int b = (t >= off) ? s[t - off] : 0;
        __syncthreads();
        s[t] = a + b;
        __syncthreads();
    }
    if (t < nb) g_bsums[t] = s[t] - v;
}

__global__ void k_scanC() {
    int i = blockIdx.x * 256 + threadIdx.x;
    if (i < NN) {
        int r = g_rowstart[i] + g_bsums[i >> 10];
        g_rowstart[i] = r;
        g_pos[i] = r;
    }
}

__global__ void k_fill(const int* __restrict__ src, const int* __restrict__ dst,
                       const float* __restrict__ w) {
    int e = blockIdx.x * 256 + threadIdx.x;
    if (e >= EE) return;
    int d = dst[e];
    int p = atomicAdd(&g_pos[d], 1);
    g_permsrc[p] = src[e];
    g_permw[p] = w[e];
}

// ---------------- aggregation: warp per node, strip-mined x4 ----------------
template <int D>
__global__ void k_aggregate(const float* __restrict__ x, float* __restrict__ agg) {
    int gt = blockIdx.x * blockDim.x + threadIdx.x;
    int node = gt >> 5;
    int lane = gt & 31;
    if (node >= NN) return;
    int start = g_rowstart[node];
    int cnt = g_deg[node];
    constexpr int NV = D / 4;
    bool act = lane < NV;
    float4 acc = make_float4(0.f, 0.f, 0.f, 0.f);
    int i = 0;
    for (; i + 4 <= cnt; i += 4) {
        int s0 = __ldg(&g_permsrc[start + i + 0]);
        int s1 = __ldg(&g_permsrc[start + i + 1]);
        int s2 = __ldg(&g_permsrc[start + i + 2]);
        int s3 = __ldg(&g_permsrc[start + i + 3]);
        float w0 = __ldg(&g_permw[start + i + 0]);
        float w1 = __ldg(&g_permw[start + i + 1]);
        float w2 = __ldg(&g_permw[start + i + 2]);
        float w3 = __ldg(&g_permw[start + i + 3]);
        if (act) {
            float4 v0 = __ldg(reinterpret_cast<const float4*>(x + (size_t)s0 * D) + lane);
            float4 v1 = __ldg(reinterpret_cast<const float4*>(x + (size_t)s1 * D) + lane);
            float4 v2 = __ldg(reinterpret_cast<const float4*>(x + (size_t)s2 * D) + lane);
            float4 v3 = __ldg(reinterpret_cast<const float4*>(x + (size_t)s3 * D) + lane);
            acc.x += v0.x * w0 + v1.x * w1 + v2.x * w2 + v3.x * w3;
            acc.y += v0.y * w0 + v1.y * w1 + v2.y * w2 + v3.y * w3;
            acc.z += v0.z * w0 + v1.z * w1 + v2.z * w2 + v3.z * w3;
            acc.w += v0.w * w0 + v1.w * w1 + v2.w * w2 + v3.w * w3;
        }
    }
    for (; i < cnt; i++) {
        int s = __ldg(&g_permsrc[start + i]);
        float wv = __ldg(&g_permw[start + i]);
        if (act) {
            float4 v = __ldg(reinterpret_cast<const float4*>(x + (size_t)s * D) + lane);
            acc.x += v.x * wv; acc.y += v.y * wv; acc.z += v.z * wv; acc.w += v.w * wv;
        }
    }
    if (act) reinterpret_cast<float4*>(agg + (size_t)node * D)[lane] = acc;
}

// ---------------- fused dual GEMM + bias + relu (f32x2, float4 smem) --------
// out[n,c] = relu( sum_k A[n,k]*Wrel[c,k] + X[n,k]*Wroot[c,k] + b[c] ), c<128
// Block: 64 rows x 128 cols, 256 threads, thread = 8 rows x 4 cols (stride 32).
template <int K>
__global__ __launch_bounds__(256, 1) void k_gemm_dual(
    const float* __restrict__ A, const float* __restrict__ X,
    const float* __restrict__ Wrel, const float* __restrict__ Wroot,
    const float* __restrict__ bias, float* __restrict__ out)
{
    constexpr int K4 = K / 4;
    constexpr int Kpad = K + 4;
    extern __shared__ __align__(16) float sm[];
    float4* Wr4 = (float4*)sm;                 // [K4][129]
    float4* Wt4 = Wr4 + K4 * 129;              // [K4][129]
    float* Aagg = (float*)(Wt4 + K4 * 129);    // [64][Kpad]
    float* Ax   = Aagg + 64 * Kpad;            // [64][Kpad]
    float* bs   = Ax + 64 * Kpad;              // [128]

    int t = threadIdx.x;
    int row0 = blockIdx.x * 64;

    // weights: coalesced gmem float4 reads, conflict-free STS.128 (129 pad)
    for (int s = t; s < 128 * K4; s += 256) {
        int c = s / K4;
        int k4 = s - c * K4;
        Wr4[k4 * 129 + c] = *(const float4*)(Wrel + c * K + 4 * k4);
        Wt4[k4 * 129 + c] = *(const float4*)(Wroot + c * K + 4 * k4);
    }
    // A / X tiles: coalesced float4
    for (int s = t; s < 64 * K4; s += 256) {
        int r = s / K4;
        int k4 = s - r * K4;
        int row = row0 + r;
        float4 va = make_float4(0.f, 0.f, 0.f, 0.f);
        float4 vx = va;
        if (row < NN) {
            va = *(const float4*)(A + (size_t)row * K + 4 * k4);
            vx = *(const float4*)(X + (size_t)row * K + 4 * k4);
        }
        *(float4*)(Aagg + r * Kpad + 4 * k4) = va;
        *(float4*)(Ax   + r * Kpad + 4 * k4) = vx;
    }
    if (t < 128) bs[t] = bias[t];
    __syncthreads();

    int tc = t & 31;
    int tr = t >> 5;
    ull acc[8][4];
#pragma unroll
    for (int i = 0; i < 8; i++)
#pragma unroll
        for (int j = 0; j < 4; j++) acc[i][j] = 0ull;

    const float* Ar = Aagg + (tr * 8) * Kpad;
    const float* Xr = Ax + (tr * 8) * Kpad;

#pragma unroll 2
    for (int k4 = 0; k4 < K4; k4++) {
        ull wRl[4], wRh[4], wTl[4], wTh[4];
#pragma unroll
        for (int j = 0; j < 4; j++) {
            float4 w = Wr4[k4 * 129 + tc + 32 * j];
            wRl[j] = pk(w.x, w.y); wRh[j] = pk(w.z, w.w);
            float4 v = Wt4[k4 * 129 + tc + 32 * j];
            wTl[j] = pk(v.x, v.y); wTh[j] = pk(v.z, v.w);
        }
#pragma unroll
        for (int i = 0; i < 8; i++) {
            float4 a4 = *(const float4*)(Ar + i * Kpad + 4 * k4);
            float4 x4 = *(const float4*)(Xr + i * Kpad + 4 * k4);
            ull al = pk(a4.x, a4.y), ah = pk(a4.z, a4.w);
            ull xl = pk(x4.x, x4.y), xh = pk(x4.z, x4.w);
#pragma unroll
            for (int j = 0; j < 4; j++) {
                fma2(acc[i][j], al, wRl[j]);
                fma2(acc[i][j], ah, wRh[j]);
                fma2(acc[i][j], xl, wTl[j]);
                fma2(acc[i][j], xh, wTh[j]);
            }
        }
    }

#pragma unroll
    for (int i = 0; i < 8; i++) {
        int row = row0 + tr * 8 + i;
        if (row >= NN) continue;
#pragma unroll
        for (int j = 0; j < 4; j++) {
            int c = tc + 32 * j;
            float lo = __uint_as_float((unsigned)acc[i][j]);
            float hi = __uint_as_float((unsigned)(acc[i][j] >> 32));
            float v = lo + hi + bs[c];
            out[(size_t)row * HID + c] = fmaxf(v, 0.f);
        }
    }
}

// ---------------- head GEMM: 64 nodes x 64 cols (47 used), K=384 ------------
// warp owns 8 rows completely (32 lanes x 2 col-groups) -> in-warp log_softmax
__global__ __launch_bounds__(256, 1) void k_head(
    const float* __restrict__ Wlin, const float* __restrict__ blin,
    float* __restrict__ out)
{
    constexpr int K = 384, K4 = 96, Kpad = 388;
    extern __shared__ __align__(16) float sm[];
    float4* W4 = (float4*)sm;              // [K4][65]
    float* Xs = (float*)(W4 + K4 * 65);    // [64][Kpad]
    float* bs = Xs + 64 * Kpad;            // [64]

    int t = threadIdx.x;
    int row0 = blockIdx.x * 64;

    // weights padded to 64 cols, coalesced gmem, conflict-free STS (65 pad)
    for (int s = t; s < 64 * K4; s += 256) {
        int c = s / K4;
        int k4 = s - c * K4;
        float4 v = make_float4(0.f, 0.f, 0.f, 0.f);
        if (c < CLS) v = *(const float4*)(Wlin + c * K + 4 * k4);
        W4[k4 * 65 + c] = v;
    }
    // gather [x1|x2|x3] rows
    for (int s = t; s < 64 * K4; s += 256) {
        int r = s / K4;
        int k4 = s - r * K4;
        int row = row0 + r;
        float4 v = make_float4(0.f, 0.f, 0.f, 0.f);
        if (row < NN) {
            if (k4 < 32)      v = *(const float4*)(g_x1 + (size_t)row * HID + 4 * k4);
            else if (k4 < 64) v = *(const float4*)(g_x2 + (size_t)row * HID + 4 * (k4 - 32));
            else              v = *(const float4*)(g_x3 + (size_t)row * HID + 4 * (k4 - 64));
        }
        *(float4*)(Xs + r * Kpad + 4 * k4) = v;
    }
    if (t < 64) bs[t] = (t < CLS) ? blin[t] : 0.f;
    __syncthreads();

    int tc = t & 31;
    int tr = t >> 5;
    ull acc[8][2];
#pragma unroll
    for (int i = 0; i < 8; i++) { acc[i][0] = 0ull; acc[i][1] = 0ull; }

    const float* Xr = Xs + (tr * 8) * Kpad;

#pragma unroll 2
    for (int k4 = 0; k4 < K4; k4++) {
        ull wl[2], wh[2];
#pragma unroll
        for (int j = 0; j < 2; j++) {
            float4 w = W4[k4 * 65 + tc + 32 * j];
            wl[j] = pk(w.x, w.y); wh[j] = pk(w.z, w.w);
        }
#pragma unroll
        for (int i = 0; i < 8; i++) {
            float4 a4 = *(const float4*)(Xr + i * Kpad + 4 * k4);
            ull al = pk(a4.x, a4.y), ah = pk(a4.z, a4.w);
#pragma unroll
            for (int j = 0; j < 2; j++) {
                fma2(acc[i][j], al, wl[j]);
                fma2(acc[i][j], ah, wh[j]);
            }
        }
    }

    bool valid1 = (tc + 32) < CLS;
#pragma unroll
    for (int i = 0; i < 8; i++) {
        int row = row0 + tr * 8 + i;
        float v0 = __uint_as_float((unsigned)acc[i][0]) +
                   __uint_as_float((unsigned)(acc[i][0] >> 32)) + bs[tc];
        float v1 = __uint_as_float((unsigned)acc[i][1]) +
                   __uint_as_float((unsigned)(acc[i][1] >> 32)) + bs[tc + 32];
        float m = valid1 ? fmaxf(v0, v1) : v0;
#pragma unroll
        for (int o = 16; o > 0; o >>= 1) m = fmaxf(m, __shfl_xor_sync(0xffffffffu, m, o));
        float se = expf(v0 - m) + (valid1 ? expf(v1 - m) : 0.f);
#pragma unroll
        for (int o = 16; o > 0; o >>= 1) se += __shfl_xor_sync(0xffffffffu, se, o);
        float lse = m + logf(se);
        if (row < NN) {
            out[(size_t)row * CLS + tc] = v0 - lse;
            if (valid1) out[(size_t)row * CLS + tc + 32] = v1 - lse;
        }
    }
}

// ---------------- launch ----------------
extern "C" void kernel_launch(void* const* d_in, const int* in_sizes, int n_in,
                              void* d_out, int out_size)
{
    const float* x0    = (const float*)d_in[0];
    const int*   ei    = (const int*)  d_in[1];
    const float* ew    = (const float*)d_in[2];
    const float* W1rel = (const float*)d_in[3];
    const float* W1rt  = (const float*)d_in[4];
    const float* b1    = (const float*)d_in[5];
    const float* W2rel = (const float*)d_in[6];
    const float* W2rt  = (const float*)d_in[7];
    const float* b2    = (const float*)d_in[8];
    const float* W3rel = (const float*)d_in[9];
    const float* W3rt  = (const float*)d_in[10];
    const float* b3    = (const float*)d_in[11];
    const float* Wlin  = (const float*)d_in[12];
    const float* blin  = (const float*)d_in[13];
    float* out = (float*)d_out;

    const int* src = ei;
    const int* dst = ei + EE;

    float *agg0p, *aggp, *x1p, *x2p, *x3p;
    cudaGetSymbolAddress((void**)&agg0p, g_agg0);
    cudaGetSymbolAddress((void**)&aggp,  g_agg);
    cudaGetSymbolAddress((void**)&x1p,   g_x1);
    cudaGetSymbolAddress((void**)&x2p,   g_x2);
    cudaGetSymbolAddress((void**)&x3p,   g_x3);

    const int smem128 = (2 * 129 * 32) * 16 + (2 * 64 * 132) * 4 + 512;  // 200192
    const int smem100 = (2 * 129 * 25) * 16 + (2 * 64 * 104) * 4 + 512;  // 156960
    const int smemH   = (96 * 65) * 16 + (64 * 388) * 4 + 256;           // 199424
    cudaFuncSetAttribute(k_gemm_dual<128>, cudaFuncAttributeMaxDynamicSharedMemorySize, smem128);
    cudaFuncSetAttribute(k_gemm_dual<100>, cudaFuncAttributeMaxDynamicSharedMemorySize, smem100);
    cudaFuncSetAttribute(k_head,           cudaFuncAttributeMaxDynamicSharedMemorySize, smemH);

    // CSR build
    k_zero_deg<<<(NN + 255) / 256, 256>>>();
    k_count<<<EE / 256, 256>>>(dst);
    k_scanA<<<(NN + 1023) / 1024, 1024>>>();
    k_scanB<<<1, 128>>>((NN + 1023) / 1024);
    k_scanC<<<(NN + 255) / 256, 256>>>();
    k_fill<<<EE / 256, 256>>>(src, dst, ew);

    const int aggBlocks = NN * 32 / 256;
    const int gemmBlocks = (NN + 63) / 64;

    // layer 1 (K = 100)
    k_aggregate<FIN><<<aggBlocks, 256>>>(x0, agg0p);
    k_gemm_dual<100><<<gemmBlocks, 256, smem100>>>(agg0p, x0, W1rel, W1rt, b1, x1p);
    // layer 2
    k_aggregate<HID><<<aggBlocks, 256>>>(x1p, aggp);
    k_gemm_dual<128><<<gemmBlocks, 256, smem128>>>(aggp, x1p, W2rel, W2rt, b2, x2p);
    // layer 3
    k_aggregate<HID><<<aggBlocks, 256>>>(x2p, aggp);
    k_gemm_dual<128><<<gemmBlocks, 256, smem128>>>(aggp, x2p, W3rel, W3rt, b3, x3p);
    // head
    k_head<<<(NN + 63) / 64, 256, smemH>>>(Wlin, blin, out);
}